// round 1
// baseline (speedup 1.0000x reference)
#include <cuda_runtime.h>

#define H 64
#define MAXN 50048
#define TILE 64
#define NTHREADS 256

// Persistent device scratch (no allocation allowed in kernel_launch).
__device__ float g_h [MAXN * H];
__device__ float g_x [MAXN * 3];
__device__ float g_Ad[MAXN * H];   // h @ e_w1[0:64]   (dst part)
__device__ float g_As[MAXN * H];   // h @ e_w1[64:128] (src part)
__device__ float g_m [MAXN * H];   // segment-sum of m_ij
__device__ float g_dx[MAXN * 3];   // segment-sum of W_ij * x_diff

__device__ __forceinline__ float silu_f(float v) {
    return v / (1.0f + __expf(-v));
}

// 64x64x64 tile GEMM: acc[4][4] += sA(64x64, row stride 68) @ sW(64x64).
// 256 threads: tx = tid&15 (cols j0=tx*4), ty = tid>>4 (rows e0=ty*4).
__device__ __forceinline__ void gemm64(const float* __restrict__ sA,
                                       const float* __restrict__ sW,
                                       int tx, int ty, float acc[4][4]) {
    const float* aRow = sA + (ty * 4) * 68;
    const float* bCol = sW + tx * 4;
#pragma unroll
    for (int k = 0; k < 64; k += 4) {
        float4 av[4], bv[4];
#pragma unroll
        for (int i = 0; i < 4; i++)
            av[i] = *(const float4*)(aRow + i * 68 + k);
#pragma unroll
        for (int kk = 0; kk < 4; kk++)
            bv[kk] = *(const float4*)(bCol + (k + kk) * 64);
#pragma unroll
        for (int i = 0; i < 4; i++) {
            float a0 = av[i].x, a1 = av[i].y, a2 = av[i].z, a3 = av[i].w;
            acc[i][0] += a0 * bv[0].x + a1 * bv[1].x + a2 * bv[2].x + a3 * bv[3].x;
            acc[i][1] += a0 * bv[0].y + a1 * bv[1].y + a2 * bv[2].y + a3 * bv[3].y;
            acc[i][2] += a0 * bv[0].z + a1 * bv[1].z + a2 * bv[2].z + a3 * bv[3].z;
            acc[i][3] += a0 * bv[0].w + a1 * bv[1].w + a2 * bv[2].w + a3 * bv[3].w;
        }
    }
}

// ---------------------------------------------------------------------------
__global__ void init_kernel(const int* __restrict__ an,
                            const float* __restrict__ pos,
                            const float* __restrict__ emb, int N) {
    int p = blockIdx.x * blockDim.x + threadIdx.x;
    int nh = N * H;
    if (p < nh) {
        int n = p >> 6, j = p & 63;
        g_h[p] = emb[an[n] * H + j];
    } else if (p < nh + N * 3) {
        int q = p - nh;
        g_x[q] = pos[q];
    }
}

// ---------------------------------------------------------------------------
// Per-layer node precompute: Ad = h@W1[0:64], As = h@W1[64:128].
// Also zeroes the m / dx accumulators for this layer.
__global__ __launch_bounds__(NTHREADS)
void node_pre_kernel(const float* __restrict__ w1, int N) {
    __shared__ float sA[TILE * 68];
    __shared__ float sW[64 * 64];
    int tid = threadIdx.x;
    int n0 = blockIdx.x * TILE;

    for (int p = tid; p < TILE * 64; p += NTHREADS) {
        int i = p >> 6, j = p & 63;
        int n = n0 + i;
        float v = 0.f;
        if (n < N) { v = g_h[n * 64 + j]; g_m[n * 64 + j] = 0.f; }
        sA[i * 68 + j] = v;
    }
    if (tid < TILE * 3) {
        int idx = n0 * 3 + tid;
        if (idx < N * 3) g_dx[idx] = 0.f;
    }
    for (int p = tid; p < 4096; p += NTHREADS) sW[p] = w1[p];
    __syncthreads();

    int tx = tid & 15, ty = tid >> 4;
    float acc[4][4];
#pragma unroll
    for (int i = 0; i < 4; i++)
#pragma unroll
        for (int j = 0; j < 4; j++) acc[i][j] = 0.f;
    gemm64(sA, sW, tx, ty, acc);
    __syncthreads();

#pragma unroll
    for (int i = 0; i < 4; i++) {
        int n = n0 + ty * 4 + i;
        if (n < N)
            *(float4*)&g_Ad[n * 64 + tx * 4] =
                make_float4(acc[i][0], acc[i][1], acc[i][2], acc[i][3]);
    }
    // second weight block (h_src part)
    for (int p = tid; p < 4096; p += NTHREADS) sW[p] = w1[4096 + p];
    __syncthreads();

#pragma unroll
    for (int i = 0; i < 4; i++)
#pragma unroll
        for (int j = 0; j < 4; j++) acc[i][j] = 0.f;
    gemm64(sA, sW, tx, ty, acc);

#pragma unroll
    for (int i = 0; i < 4; i++) {
        int n = n0 + ty * 4 + i;
        if (n < N)
            *(float4*)&g_As[n * 64 + tx * 4] =
                make_float4(acc[i][0], acc[i][1], acc[i][2], acc[i][3]);
    }
}

// ---------------------------------------------------------------------------
// Edge kernel: t1 = silu(Ad[dst]+As[src]+r*w1r+b1); m = silu(t1@w2+b2);
// scatter m -> g_m[dst]; u = silu(m@xw1+xb1); W = u.xw2+xb2;
// scatter W*x_diff -> g_dx[dst].
__global__ __launch_bounds__(NTHREADS)
void edge_kernel(const int* __restrict__ src, const int* __restrict__ dst,
                 const float* __restrict__ w1r, const float* __restrict__ b1,
                 const float* __restrict__ w2,  const float* __restrict__ b2,
                 const float* __restrict__ xw1, const float* __restrict__ xb1,
                 const float* __restrict__ xw2, const float* __restrict__ xb2,
                 int E) {
    __shared__ float sA[TILE * 68];
    __shared__ float sW[64 * 64];
    __shared__ float sxd[TILE * 3];
    __shared__ float sr[TILE];
    __shared__ float sWe[TILE];
    __shared__ int   sdst[TILE];
    __shared__ int   ssrc[TILE];
    __shared__ float sw1r[64], sb1[64], sb2[64], sxb1[64], sxw2[64];

    int tid = threadIdx.x;
    int e0  = blockIdx.x * TILE;

    if (tid < TILE) {
        int eg = e0 + tid;
        if (eg < E) {
            int s = src[eg], d = dst[eg];
            ssrc[tid] = s; sdst[tid] = d;
            float d0 = g_x[s * 3 + 0] - g_x[d * 3 + 0];
            float d1 = g_x[s * 3 + 1] - g_x[d * 3 + 1];
            float d2 = g_x[s * 3 + 2] - g_x[d * 3 + 2];
            sxd[tid * 3 + 0] = d0; sxd[tid * 3 + 1] = d1; sxd[tid * 3 + 2] = d2;
            sr[tid] = sqrtf(d0 * d0 + d1 * d1 + d2 * d2);
        } else {
            ssrc[tid] = 0; sdst[tid] = -1;
            sxd[tid * 3 + 0] = 0.f; sxd[tid * 3 + 1] = 0.f; sxd[tid * 3 + 2] = 0.f;
            sr[tid] = 0.f;
        }
        sWe[tid] = xb2[0];
    }
    if (tid >= 64 && tid < 128) {
        int j = tid - 64;
        sw1r[j] = w1r[j]; sb1[j] = b1[j]; sb2[j] = b2[j];
        sxb1[j] = xb1[j]; sxw2[j] = xw2[j];
    }
    for (int p = tid; p < 4096; p += NTHREADS) sW[p] = w2[p];
    __syncthreads();

    // stage 1: t1
    for (int p = tid; p < 4096; p += NTHREADS) {
        int e = p >> 6, j = p & 63;
        int d = sdst[e];
        int dd = d < 0 ? 0 : d;
        int s  = ssrc[e];
        float v = g_Ad[dd * 64 + j] + g_As[s * 64 + j] + sr[e] * sw1r[j] + sb1[j];
        sA[e * 68 + j] = silu_f(v);
    }
    __syncthreads();

    int tx = tid & 15, ty = tid >> 4;
    float acc[4][4];
#pragma unroll
    for (int i = 0; i < 4; i++)
#pragma unroll
        for (int j = 0; j < 4; j++) acc[i][j] = 0.f;
    gemm64(sA, sW, tx, ty, acc);
    __syncthreads();   // all reads of sA/sW done

    // m = silu(acc + b2); store into sA; scatter to g_m
#pragma unroll
    for (int i = 0; i < 4; i++) {
        int e = ty * 4 + i;
        int d = sdst[e];
        float m0 = silu_f(acc[i][0] + sb2[tx * 4 + 0]);
        float m1 = silu_f(acc[i][1] + sb2[tx * 4 + 1]);
        float m2 = silu_f(acc[i][2] + sb2[tx * 4 + 2]);
        float m3 = silu_f(acc[i][3] + sb2[tx * 4 + 3]);
        *(float4*)&sA[e * 68 + tx * 4] = make_float4(m0, m1, m2, m3);
        if (d >= 0) {
            atomicAdd(&g_m[d * 64 + tx * 4 + 0], m0);
            atomicAdd(&g_m[d * 64 + tx * 4 + 1], m1);
            atomicAdd(&g_m[d * 64 + tx * 4 + 2], m2);
            atomicAdd(&g_m[d * 64 + tx * 4 + 3], m3);
        }
    }
    for (int p = tid; p < 4096; p += NTHREADS) sW[p] = xw1[p];
    __syncthreads();

#pragma unroll
    for (int i = 0; i < 4; i++)
#pragma unroll
        for (int j = 0; j < 4; j++) acc[i][j] = 0.f;
    gemm64(sA, sW, tx, ty, acc);

    // u = silu(acc + xb1); partial W = u . xw2
    float part[4];
#pragma unroll
    for (int i = 0; i < 4; i++) {
        float pp = 0.f;
#pragma unroll
        for (int jj = 0; jj < 4; jj++) {
            float u = silu_f(acc[i][jj] + sxb1[tx * 4 + jj]);
            pp += u * sxw2[tx * 4 + jj];
        }
        part[i] = pp;
    }
    // reduce across the 16 tx lanes (lane bit 4 = ty parity, untouched)
#pragma unroll
    for (int off = 8; off >= 1; off >>= 1)
#pragma unroll
        for (int i = 0; i < 4; i++)
            part[i] += __shfl_xor_sync(0xffffffffu, part[i], off);
    if (tx == 0) {
#pragma unroll
        for (int i = 0; i < 4; i++) atomicAdd(&sWe[ty * 4 + i], part[i]);
    }
    __syncthreads();

    if (tid < TILE * 3) {
        int e = tid / 3, c = tid - e * 3;
        int d = sdst[e];
        if (d >= 0) atomicAdd(&g_dx[d * 3 + c], sWe[e] * sxd[e * 3 + c]);
    }
}

// ---------------------------------------------------------------------------
// Node update: h += silu([h,m]@h_w1 + b1) @ h_w2 + b2 ; x += dx
__global__ __launch_bounds__(NTHREADS)
void node_update_kernel(const float* __restrict__ hw1, const float* __restrict__ hb1,
                        const float* __restrict__ hw2, const float* __restrict__ hb2,
                        int N) {
    __shared__ float sA[TILE * 68];
    __shared__ float sW[64 * 64];
    int tid = threadIdx.x;
    int n0 = blockIdx.x * TILE;
    int tx = tid & 15, ty = tid >> 4;

    // pass A: h part
    for (int p = tid; p < TILE * 64; p += NTHREADS) {
        int i = p >> 6, j = p & 63;
        int n = n0 + i;
        sA[i * 68 + j] = (n < N) ? g_h[n * 64 + j] : 0.f;
    }
    for (int p = tid; p < 4096; p += NTHREADS) sW[p] = hw1[p];
    __syncthreads();

    float acc[4][4];
#pragma unroll
    for (int i = 0; i < 4; i++)
#pragma unroll
        for (int j = 0; j < 4; j++) acc[i][j] = 0.f;
    gemm64(sA, sW, tx, ty, acc);
    __syncthreads();

    // pass B: m part (accumulate)
    for (int p = tid; p < TILE * 64; p += NTHREADS) {
        int i = p >> 6, j = p & 63;
        int n = n0 + i;
        sA[i * 68 + j] = (n < N) ? g_m[n * 64 + j] : 0.f;
    }
    for (int p = tid; p < 4096; p += NTHREADS) sW[p] = hw1[4096 + p];
    __syncthreads();
    gemm64(sA, sW, tx, ty, acc);
    __syncthreads();

    // t = silu(acc + hb1) -> sA ; load h_w2
#pragma unroll
    for (int i = 0; i < 4; i++) {
        int e = ty * 4 + i;
        float t0 = silu_f(acc[i][0] + hb1[tx * 4 + 0]);
        float t1 = silu_f(acc[i][1] + hb1[tx * 4 + 1]);
        float t2 = silu_f(acc[i][2] + hb1[tx * 4 + 2]);
        float t3 = silu_f(acc[i][3] + hb1[tx * 4 + 3]);
        *(float4*)&sA[e * 68 + tx * 4] = make_float4(t0, t1, t2, t3);
    }
    for (int p = tid; p < 4096; p += NTHREADS) sW[p] = hw2[p];
    __syncthreads();

#pragma unroll
    for (int i = 0; i < 4; i++)
#pragma unroll
        for (int j = 0; j < 4; j++) acc[i][j] = 0.f;
    gemm64(sA, sW, tx, ty, acc);

#pragma unroll
    for (int i = 0; i < 4; i++) {
        int n = n0 + ty * 4 + i;
        if (n < N) {
            float4 old = *(float4*)&g_h[n * 64 + tx * 4];
            old.x += acc[i][0] + hb2[tx * 4 + 0];
            old.y += acc[i][1] + hb2[tx * 4 + 1];
            old.z += acc[i][2] + hb2[tx * 4 + 2];
            old.w += acc[i][3] + hb2[tx * 4 + 3];
            *(float4*)&g_h[n * 64 + tx * 4] = old;
        }
    }
    if (tid < TILE * 3) {
        int idx = n0 * 3 + tid;
        if (idx < N * 3) g_x[idx] += g_dx[idx];
    }
}

// ---------------------------------------------------------------------------
__global__ void copy_out_kernel(float* __restrict__ out, int N) {
    int p = blockIdx.x * blockDim.x + threadIdx.x;
    int nh = N * H;
    if (p < nh) out[p] = g_h[p];
    else if (p < nh + N * 3) out[p] = g_x[p - nh];
}

// ---------------------------------------------------------------------------
extern "C" void kernel_launch(void* const* d_in, const int* in_sizes, int n_in,
                              void* d_out, int out_size) {
    const int*   an   = (const int*)d_in[0];
    const float* pos  = (const float*)d_in[1];
    const int*   eidx = (const int*)d_in[2];
    // d_in[3] = edge_attr (unused by reference)
    const float* emb  = (const float*)d_in[4];
    const float* e_w1 = (const float*)d_in[5];
    const float* e_b1 = (const float*)d_in[6];
    const float* e_w2 = (const float*)d_in[7];
    const float* e_b2 = (const float*)d_in[8];
    const float* h_w1 = (const float*)d_in[9];
    const float* h_b1 = (const float*)d_in[10];
    const float* h_w2 = (const float*)d_in[11];
    const float* h_b2 = (const float*)d_in[12];
    const float* x_w1 = (const float*)d_in[13];
    const float* x_b1 = (const float*)d_in[14];
    const float* x_w2 = (const float*)d_in[15];
    const float* x_b2 = (const float*)d_in[16];

    int N = in_sizes[0];
    int E = in_sizes[2] / 2;
    float* out = (float*)d_out;

    int nodeBlocks = (N + TILE - 1) / TILE;
    int edgeBlocks = (E + TILE - 1) / TILE;
    int totBlocks  = (N * 67 + 255) / 256;

    init_kernel<<<totBlocks, 256>>>(an, pos, emb, N);

    for (int l = 0; l < 2; l++) {
        const float* ew1l = e_w1 + l * 129 * 64;
        node_pre_kernel<<<nodeBlocks, NTHREADS>>>(ew1l, N);
        edge_kernel<<<edgeBlocks, NTHREADS>>>(
            eidx, eidx + E,
            ew1l + 128 * 64, e_b1 + l * 64,
            e_w2 + l * 4096, e_b2 + l * 64,
            x_w1 + l * 4096, x_b1 + l * 64,
            x_w2 + l * 64, x_b2 + l,
            E);
        node_update_kernel<<<nodeBlocks, NTHREADS>>>(
            h_w1 + l * 128 * 64, h_b1 + l * 64,
            h_w2 + l * 4096, h_b2 + l * 64, N);
    }

    copy_out_kernel<<<totBlocks, 256>>>(out, N);
}